// round 1
// baseline (speedup 1.0000x reference)
#include <cuda_runtime.h>

#define BB 16
#define MM 2048
#define SS 6
#define EE 128
#define LCC 512
#define VV 32000
#define BM (BB*MM)        // 32768
#define VE (VV*EE)        // 4096000
#define BME (BM*EE)       // 4194304

// ---------------- scratch (static device memory; no allocations) ----------------
__device__ float g_bag[3u*BME];     // gathered+add_lm bags, [k][g][e]
__device__ float g_mg[3u*BME];      // MLP(bag)*gp,          [k][g][e]
__device__ float g_tb[BB*EE];       // tf@wA1_bottom + bA1
__device__ float g_u[2][BB*EE];     // ping-pong query state
__device__ float g_logits[BM];
__device__ float g_soft[BM];
__device__ float g_part[16][BB*EE]; // chunked u-update partials

// ---------------- f32x2 helpers ----------------
__device__ __forceinline__ unsigned long long pack2(float lo, float hi){
    unsigned long long r;
    asm("mov.b64 %0, {%1,%2};" : "=l"(r) : "f"(lo), "f"(hi));
    return r;
}
__device__ __forceinline__ float2 unpack2(unsigned long long v){
    float2 r;
    asm("mov.b64 {%0,%1}, %2;" : "=f"(r.x), "=f"(r.y) : "l"(v));
    return r;
}
__device__ __forceinline__ void fma2(unsigned long long &d, unsigned long long a, unsigned long long b){
    asm("fma.rn.f32x2 %0, %1, %2, %0;" : "+l"(d) : "l"(a), "l"(b));
}

// swizzled shared address for transposed [e][r] tiles (stride 128 floats)
__device__ __forceinline__ int smaddr(int e, int r){
    return e*128 + (r ^ (((((e>>3)^e))&7)<<2));
}

// ---------------- k_init: tb[b][j] = bA1[j] + sum_e tf[b][e]*wA1[128+e][j]; u0 = q ----------------
__global__ void k_init(const float* __restrict__ tf, const float* __restrict__ wA1,
                       const float* __restrict__ bA1, const float* __restrict__ q){
    int b = blockIdx.x, j = threadIdx.x;
    float acc = bA1[j];
#pragma unroll 8
    for (int e = 0; e < EE; e++)
        acc += tf[b*EE + e] * wA1[(EE + e)*EE + j];
    g_tb[b*EE + j] = acc;
    g_u[0][b*EE + j] = q[b*EE + j];
}

// ---------------- k_gather: bag[k][g][e] = sum_s C[k][story[g][s]][e] + add_lm ----------------
__global__ void k_gather(const int* __restrict__ story, const int* __restrict__ kb_len,
                         const int* __restrict__ conv_len, const float* __restrict__ dh,
                         const float* __restrict__ C){
    int tid = threadIdx.x;
    int e = tid & (EE-1);
    int g = blockIdx.x*2 + (tid >> 7);
    int b = g >> 11, m = g & (MM-1);
    const int* st = story + g*SS;
    int t0 = st[0], t1 = st[1], t2 = st[2], t3 = st[3], t4 = st[4], t5 = st[5];
    float dhv = 0.f;
    int idx = m - kb_len[b];
    if (idx >= 0 && idx < conv_len[b])
        dhv = dh[(b*LCC + idx)*EE + e];
#pragma unroll
    for (int k = 0; k < 3; k++){
        const float* Ck = C + k*VE;
        float acc = Ck[t0*EE+e] + Ck[t1*EE+e] + Ck[t2*EE+e]
                  + Ck[t3*EE+e] + Ck[t4*EE+e] + Ck[t5*EE+e];
        g_bag[k*BME + g*EE + e] = acc + dhv;
    }
}

// ---------------- fused MLP: mg[k] = (lrelu(bag[k]@W1top + tb) @ W2 + bA2) * gp ----------------
__device__ __forceinline__ void gemm_tile(const float* __restrict__ As, const float* __restrict__ Ws,
                                          int r0, int c0, unsigned long long acc[8][4]){
#pragma unroll 8
    for (int kk = 0; kk < 128; kk++){
        int xb = ((((kk>>3)^kk)&7)<<2);
        const float* ap = As + kk*128;
        float4 a0 = *(const float4*)(ap + (r0 ^ xb));
        float4 a1 = *(const float4*)(ap + ((r0+4) ^ xb));
        const float* bp = Ws + kk*EE + c0;
        float4 b0 = *(const float4*)bp;
        float4 b1 = *(const float4*)(bp+4);
        unsigned long long bbp[4];
        bbp[0] = pack2(b0.x, b0.y); bbp[1] = pack2(b0.z, b0.w);
        bbp[2] = pack2(b1.x, b1.y); bbp[3] = pack2(b1.z, b1.w);
        float av[8] = {a0.x,a0.y,a0.z,a0.w,a1.x,a1.y,a1.z,a1.w};
#pragma unroll
        for (int ii = 0; ii < 8; ii++){
            unsigned long long ad = pack2(av[ii], av[ii]);
#pragma unroll
            for (int jp = 0; jp < 4; jp++) fma2(acc[ii][jp], ad, bbp[jp]);
        }
    }
}

__global__ void __launch_bounds__(256, 1)
k_mlp(const float* __restrict__ wA1, const float* __restrict__ wA2,
      const float* __restrict__ bA2, const float* __restrict__ gp){
    extern __shared__ float sm[];
    float* Xs  = sm;                 // [128][128] k-major swizzled
    float* Y1s = sm + 128*128;       // [128][128] k-major swizzled
    float* Ws  = sm + 2*128*128;     // [128][128] row-major
    int k    = blockIdx.y;
    int g0   = blockIdx.x * 128;
    int b    = g0 >> 11;
    int tid  = threadIdx.x;
    const float* bag = g_bag + k*BME + g0*EE;

    // load X transposed into Xs (swizzled): thread e = tid&127, rows step 2
    {
        int e  = tid & 127;
        int rh = tid >> 7;
        int xb = ((((e>>3)^e)&7)<<2);
        for (int r = rh; r < 128; r += 2)
            Xs[e*128 + (r ^ xb)] = bag[r*EE + e];
    }
    for (int i = tid; i < EE*EE/4; i += 256)
        ((float4*)Ws)[i] = ((const float4*)wA1)[i];   // top half rows 0..127
    __syncthreads();

    int tx = tid & 15, ty = tid >> 4;
    int r0 = ty*8, c0 = tx*8;
    unsigned long long acc[8][4];
#pragma unroll
    for (int ii=0; ii<8; ii++)
#pragma unroll
        for (int jp=0; jp<4; jp++) acc[ii][jp] = 0ull;

    gemm_tile(Xs, Ws, r0, c0, acc);

    // epilogue 1: +tb, lrelu, store transposed into Y1s (swizzled)
    {
        float tbv[8];
        *(float4*)&tbv[0] = *(const float4*)(g_tb + b*EE + c0);
        *(float4*)&tbv[4] = *(const float4*)(g_tb + b*EE + c0 + 4);
        float y[8][8];
#pragma unroll
        for (int ii=0; ii<8; ii++)
#pragma unroll
            for (int jp=0; jp<4; jp++){
                float2 p = unpack2(acc[ii][jp]);
                float y0 = p.x + tbv[jp*2],  y1v = p.y + tbv[jp*2+1];
                y[ii][jp*2]   = y0  > 0.f ? y0  : 0.1f*y0;
                y[ii][jp*2+1] = y1v > 0.f ? y1v : 0.1f*y1v;
            }
#pragma unroll
        for (int jj=0; jj<8; jj++){
            int c = c0 + jj;
            int xb = ((((c>>3)^c)&7)<<2);
            *(float4*)&Y1s[c*128 + (r0 ^ xb)]     = make_float4(y[0][jj],y[1][jj],y[2][jj],y[3][jj]);
            *(float4*)&Y1s[c*128 + ((r0+4) ^ xb)] = make_float4(y[4][jj],y[5][jj],y[6][jj],y[7][jj]);
        }
    }
    __syncthreads();
    for (int i = tid; i < EE*EE/4; i += 256)
        ((float4*)Ws)[i] = ((const float4*)wA2)[i];
    __syncthreads();

#pragma unroll
    for (int ii=0; ii<8; ii++)
#pragma unroll
        for (int jp=0; jp<4; jp++) acc[ii][jp] = 0ull;

    gemm_tile(Y1s, Ws, r0, c0, acc);

    // epilogue 2: +bA2, *gp, write mg
    {
        float bv[8];
        *(float4*)&bv[0] = *(const float4*)(bA2 + c0);
        *(float4*)&bv[4] = *(const float4*)(bA2 + c0 + 4);
#pragma unroll
        for (int ii=0; ii<8; ii++){
            float gv = __ldg(gp + g0 + r0 + ii);
            float o[8];
#pragma unroll
            for (int jp=0; jp<4; jp++){
                float2 p = unpack2(acc[ii][jp]);
                o[jp*2]   = (p.x + bv[jp*2])   * gv;
                o[jp*2+1] = (p.y + bv[jp*2+1]) * gv;
            }
            float* op = g_mg + k*BME + (g0 + r0 + ii)*EE + c0;
            *(float4*)op     = make_float4(o[0],o[1],o[2],o[3]);
            *(float4*)(op+4) = make_float4(o[4],o[5],o[6],o[7]);
        }
    }
}

// ---------------- phase 2 ----------------
__global__ void k_logits(int k, int usel, float* extra){
    int g = blockIdx.x*8 + (threadIdx.x >> 5);
    int lane = threadIdx.x & 31;
    int b = g >> 11;
    const float* mg = g_mg + (size_t)k*BME + (size_t)g*EE;
    const float* u  = g_u[usel] + b*EE;
    float4 x  = *(const float4*)(mg + lane*4);
    float4 uv = *(const float4*)(u  + lane*4);
    float p = x.x*uv.x + x.y*uv.y + x.z*uv.z + x.w*uv.w;
#pragma unroll
    for (int o = 16; o; o >>= 1) p += __shfl_xor_sync(0xffffffffu, p, o);
    if (!lane){
        g_logits[g] = p;
        if (extra) extra[g] = p;
    }
}

__global__ void k_softmax(float* extra){
    __shared__ float red[512];
    int b = blockIdx.x, tid = threadIdx.x;
    const float* l = g_logits + b*MM;
    float v[4];
#pragma unroll
    for (int i=0;i<4;i++) v[i] = l[tid + i*512];
    float mx = fmaxf(fmaxf(v[0],v[1]), fmaxf(v[2],v[3]));
    red[tid] = mx; __syncthreads();
    for (int s=256; s; s>>=1){ if (tid < s) red[tid] = fmaxf(red[tid], red[tid+s]); __syncthreads(); }
    mx = red[0]; __syncthreads();
    float e[4], ssum = 0.f;
#pragma unroll
    for (int i=0;i<4;i++){ e[i] = expf(v[i] - mx); ssum += e[i]; }
    red[tid] = ssum; __syncthreads();
    for (int s=256; s; s>>=1){ if (tid < s) red[tid] += red[tid+s]; __syncthreads(); }
    float inv = 1.f / red[0];
#pragma unroll
    for (int i=0;i<4;i++){
        float sv = e[i]*inv;
        g_soft[b*MM + tid + i*512] = sv;
        if (extra) extra[b*MM + tid + i*512] = sv;
    }
}

__global__ void k_upart(int k){
    int chunk = blockIdx.x, b = blockIdx.y, e = threadIdx.x;
    int m0 = chunk*128;
    const float* mp = g_mg + (size_t)k*BME + ((size_t)(b*MM + m0))*EE + e;
    const float* sp = g_soft + b*MM + m0;
    float acc = 0.f;
#pragma unroll 4
    for (int i=0;i<128;i++) acc += mp[i*EE] * sp[i];
    g_part[chunk][b*EE + e] = acc;
}

__global__ void k_ufinal(int uin, int uout){
    int b = blockIdx.x, e = threadIdx.x;
    float acc = g_u[uin][b*EE + e];
#pragma unroll
    for (int c=0;c<16;c++) acc += g_part[c][b*EE + e];
    g_u[uout][b*EE + e] = acc;
}

// ---------------- launch ----------------
extern "C" void kernel_launch(void* const* d_in, const int* in_sizes, int n_in,
                              void* d_out, int out_size){
    const int*   story    = (const int*)  d_in[0];
    const int*   kb_len   = (const int*)  d_in[1];
    const int*   conv_len = (const int*)  d_in[2];
    // d_in[3] = hidden (dead code)
    const float* dh       = (const float*)d_in[4];
    const float* tf       = (const float*)d_in[5];
    const float* q        = (const float*)d_in[6];
    const float* gp       = (const float*)d_in[7];
    const float* C        = (const float*)d_in[8];
    const float* wA1      = (const float*)d_in[9];
    const float* bA1      = (const float*)d_in[10];
    const float* wA2      = (const float*)d_in[11];
    const float* bA2      = (const float*)d_in[12];
    // d_in[13..18] = wC1,bC1,wC2,bC2,wf,bf (dead code)
    float* out = (float*)d_out;   // [0:BM) prob_soft, [BM:2BM) prob_logits

    const int SMEM = 3*128*128*4; // 192KB
    cudaFuncSetAttribute(k_mlp, cudaFuncAttributeMaxDynamicSharedMemorySize, SMEM);

    k_init  <<<BB, EE>>>(tf, wA1, bA1, q);
    k_gather<<<BM/2, 256>>>(story, kb_len, conv_len, dh, C);
    k_mlp   <<<dim3(256,3), 256, SMEM>>>(wA1, wA2, bA2, gp);

    // hop 0
    k_logits <<<BM/8, 256>>>(0, 0, nullptr);
    k_softmax<<<BB, 512>>>(nullptr);
    k_upart  <<<dim3(16,BB), EE>>>(1);
    k_ufinal <<<BB, EE>>>(0, 1);
    // hop 1
    k_logits <<<BM/8, 256>>>(1, 1, nullptr);
    k_softmax<<<BB, 512>>>(nullptr);
    k_upart  <<<dim3(16,BB), EE>>>(2);
    k_ufinal <<<BB, EE>>>(1, 0);
    // hop 2 (final outputs; uq update is dead)
    k_logits <<<BM/8, 256>>>(2, 0, out + BM);
    k_softmax<<<BB, 512>>>(out);
}